// round 16
// baseline (speedup 1.0000x reference)
#include <cuda_runtime.h>

// Problem constants: B=32, H=8, E=64, L=1024, MODES=64, OUT/8=64
#define BHN 256           // B*H
typedef unsigned long long u64;

// Scratch (allocation-free: device globals).
__device__ float2 g_Xq[BHN * 4096];
__device__ float2 g_Xk[BHN * 4096];
__device__ float2 g_Xqkv[BHN * 4096];
__device__ float2 g_Xw[BHN * 4096];

// ---- packed f32x2 helpers (Blackwell FFMA2 path) ----
__device__ __forceinline__ u64 pk2(float lo, float hi) {
    u64 r; asm("mov.b64 %0,{%1,%2};" : "=l"(r) : "f"(lo), "f"(hi)); return r;
}
__device__ __forceinline__ float2 upk2(u64 v) {
    float2 r; asm("mov.b64 {%0,%1},%2;" : "=f"(r.x), "=f"(r.y) : "l"(v)); return r;
}
__device__ __forceinline__ u64 ffma2(u64 a, u64 b, u64 c) {
    u64 d; asm("fma.rn.f32x2 %0,%1,%2,%3;" : "=l"(d) : "l"(a), "l"(b), "l"(c)); return d;
}
__device__ __forceinline__ u64 fadd2(u64 a, u64 b) {
    u64 d; asm("add.rn.f32x2 %0,%1,%2;" : "=l"(d) : "l"(a), "l"(b)); return d;
}

// ============================================================================
// K1: pruned rDFT, radix-2 decimation.
// NEW: x operands pre-duplicated as u64 (v,v) in smem with permuted layout
//   pos(e) = (e%4)*16 + e/4, row pitch 65 u64:
//   - compute LDS.64 banks = 2*eg (16 distinct, broadcast across half-warps)
//   - staging STS.64 banks = (2l + 2e4) mod 32 (all 32 lanes distinct)
// Removes the 8 pk2 MOVs per inner iteration (issue/alu relief).
// Tiling (4e x 4m), accumulators, 2-level sums unchanged. Chunk = 32 l.
// ============================================================================
__global__ __launch_bounds__(256) void k_dft(const float* __restrict__ qp,
                                             const float* __restrict__ kp)
{
    __shared__ float2 tw[1024];     // 8KB
    __shared__ u64 ss[32 * 65];     // dup'd s chunk [l][pos(e)] pitch 65 (16.6KB)
    __shared__ u64 dd[32 * 65];     // dup'd d chunk (16.6KB)
    const int tid = threadIdx.x;
    const int bh = blockIdx.x;
    const int b = bh >> 3, h = bh & 7;
    const float* src = (blockIdx.y == 0 ? qp : kp) + (size_t)b * 524288 + h * 64;
    float2* dst = (blockIdx.y == 0 ? g_Xq : g_Xk) + (size_t)bh * 4096;

    for (int k0 = tid; k0 < 1024; k0 += 256) {
        float s, c;
        sincosf(-6.2831853071795864769f * (float)k0 * (1.0f / 1024.0f), &s, &c);
        tw[k0] = make_float2(c, s);
    }

    const int eg = tid & 15;       // e group: e = eg*4 + i   (varies per lane)
    const int mg = tid >> 4;       // m group: m = mg + 16*j  (const per half-warp)
    const u64* yb = ((mg & 1) ? dd : ss) + eg;   // parity(m) == parity(mg)

    // staging indices: this thread stages slots tid and tid+256
    const int sl0 = tid >> 4;      // l rows 0..15 (and +16)
    const int se4 = tid & 15;      // e-quad

    u64 acc[4][4];
#pragma unroll
    for (int i = 0; i < 4; i++)
#pragma unroll
        for (int j = 0; j < 4; j++) acc[i][j] = 0ULL;

    for (int c0 = 0; c0 < 16; c0++) {
        __syncthreads();
#pragma unroll
        for (int t = 0; t < 2; t++) {
            int l = sl0 + t * 16;
            size_t off = (size_t)(c0 * 32 + l) * 512 + se4 * 4;
            float4 a  = *(const float4*)(src + off);
            float4 b4 = *(const float4*)(src + off + 262144);   // l+512
            // value for e = se4*4 + c goes to position c*16 + se4
            u64* sp = &ss[l * 65 + se4];
            u64* dp = &dd[l * 65 + se4];
            float v;
            v = a.x + b4.x; sp[0]  = pk2(v, v);
            v = a.y + b4.y; sp[16] = pk2(v, v);
            v = a.z + b4.z; sp[32] = pk2(v, v);
            v = a.w + b4.w; sp[48] = pk2(v, v);
            v = a.x - b4.x; dp[0]  = pk2(v, v);
            v = a.y - b4.y; dp[16] = pk2(v, v);
            v = a.z - b4.z; dp[32] = pk2(v, v);
            v = a.w - b4.w; dp[48] = pk2(v, v);
        }
        __syncthreads();

        u64 cacc[4][4];   // chunk accumulators (2-level sum: fp32 accuracy)
#pragma unroll
        for (int i = 0; i < 4; i++)
#pragma unroll
            for (int j = 0; j < 4; j++) cacc[i][j] = 0ULL;

#pragma unroll 8
        for (int l = 0; l < 32; l++) {
            const int lg = c0 * 32 + l;
            // e = eg*4 + i lives at [l][i*16 + eg]
            u64 x0 = yb[l * 65];
            u64 x1 = yb[l * 65 + 16];
            u64 x2 = yb[l * 65 + 32];
            u64 x3 = yb[l * 65 + 48];
            int kk = (mg * lg) & 1023;
            const int dk = (lg << 4) & 1023;
#pragma unroll
            for (int j = 0; j < 4; j++) {
                u64 t = *(const u64*)&tw[kk];
                cacc[0][j] = ffma2(x0, t, cacc[0][j]);
                cacc[1][j] = ffma2(x1, t, cacc[1][j]);
                cacc[2][j] = ffma2(x2, t, cacc[2][j]);
                cacc[3][j] = ffma2(x3, t, cacc[3][j]);
                kk = (kk + dk) & 1023;
            }
        }
#pragma unroll
        for (int i = 0; i < 4; i++)
#pragma unroll
            for (int j = 0; j < 4; j++) acc[i][j] = fadd2(acc[i][j], cacc[i][j]);
    }

#pragma unroll
    for (int i = 0; i < 4; i++)
#pragma unroll
        for (int j = 0; j < 4; j++)
            dst[(eg * 4 + i) * 64 + (mg + 16 * j)] = upk2(acc[i][j]);
}

// ============================================================================
// K2 (fused qk + qkv) — UNCHANGED from Round 12:
//   phase 1: xqk[x,y] = sum_e Xq[e,x]*Xk[e,y]; complex tanh -> T (in smem)
//   phase 2: xqkv[e,x] = sum_y T[x,y]*Xk[e,y]
// ============================================================================
__global__ __launch_bounds__(256) void k_qk2(void)
{
    __shared__ float2 buf[4096];     // phase1: Aq|Ak; phase2: Ts pitch 64
    __shared__ float2 Bk[64 * 17];   // [e][yy] pitch 17
    const int tid = threadIdx.x, bh = blockIdx.x;
    const float2* xq = g_Xq + (size_t)bh * 4096;
    const float2* xk = g_Xk + (size_t)bh * 4096;
    const int xg = tid & 15, yg = tid >> 4;

    float2 c[4][4];
#pragma unroll
    for (int i = 0; i < 4; i++)
#pragma unroll
        for (int j = 0; j < 4; j++) c[i][j] = make_float2(0.f, 0.f);

    for (int s = 0; s < 2; s++) {
        __syncthreads();
        for (int idx = tid; idx < 2048; idx += 256) {
            buf[idx]        = xq[s * 2048 + idx];
            buf[2048 + idx] = xk[s * 2048 + idx];
        }
        __syncthreads();
        for (int e = 0; e < 32; e++) {
            float4 a01 = *(const float4*)&buf[e * 64 + xg * 4];
            float4 a23 = *(const float4*)&buf[e * 64 + xg * 4 + 2];
            float4 b01 = *(const float4*)&buf[2048 + e * 64 + yg * 4];
            float4 b23 = *(const float4*)&buf[2048 + e * 64 + yg * 4 + 2];
            float2 aq[4] = { {a01.x,a01.y},{a01.z,a01.w},{a23.x,a23.y},{a23.z,a23.w} };
            float2 ak[4] = { {b01.x,b01.y},{b01.z,b01.w},{b23.x,b23.y},{b23.z,b23.w} };
#pragma unroll
            for (int i = 0; i < 4; i++)
#pragma unroll
                for (int j = 0; j < 4; j++) {
                    c[i][j].x += aq[i].x * ak[j].x;
                    c[i][j].x -= aq[i].y * ak[j].y;
                    c[i][j].y += aq[i].x * ak[j].y;
                    c[i][j].y += aq[i].y * ak[j].x;
                }
        }
    }

    float2 treg[4][4];
#pragma unroll
    for (int i = 0; i < 4; i++)
#pragma unroll
        for (int j = 0; j < 4; j++) {
            float t = tanhf(c[i][j].x);
            float u = tanf(c[i][j].y);
            float u2 = u * u;
            float rr, ii;
            if (!(u2 < 1e30f)) { rr = 1.0f / t; ii = 0.0f; }
            else {
                float inv = 1.0f / fmaf(t * t, u2, 1.0f);
                rr = t * (1.0f + u2) * inv;
                ii = u * (1.0f - t * t) * inv;
            }
            treg[i][j] = make_float2(rr, ii);
        }
    __syncthreads();                 // all phase-1 reads of buf done
#pragma unroll
    for (int i = 0; i < 4; i++)
#pragma unroll
        for (int j = 0; j < 4; j++)
            buf[(xg * 4 + i) * 64 + yg * 4 + j] = treg[i][j];   // Ts[x][y]

    const int eg2 = tid & 15, xg2 = tid >> 4;   // e = eg2+16i, x = xg2*4+j
    float2 c2[4][4];
#pragma unroll
    for (int i = 0; i < 4; i++)
#pragma unroll
        for (int j = 0; j < 4; j++) c2[i][j] = make_float2(0.f, 0.f);

    for (int ys = 0; ys < 4; ys++) {
        __syncthreads();
        for (int idx = tid; idx < 1024; idx += 256) {
            int r = idx >> 4, yy = idx & 15;
            Bk[r * 17 + yy] = xk[r * 64 + ys * 16 + yy];
        }
        __syncthreads();
        for (int y = 0; y < 16; y++) {
            float2 kv[4], tt[4];
#pragma unroll
            for (int i = 0; i < 4; i++) kv[i] = Bk[(eg2 + 16 * i) * 17 + y];
#pragma unroll
            for (int j = 0; j < 4; j++) tt[j] = buf[(xg2 * 4 + j) * 64 + ys * 16 + y];
#pragma unroll
            for (int i = 0; i < 4; i++)
#pragma unroll
                for (int j = 0; j < 4; j++) {
                    c2[i][j].x += tt[j].x * kv[i].x;
                    c2[i][j].x -= tt[j].y * kv[i].y;
                    c2[i][j].y += tt[j].x * kv[i].y;
                    c2[i][j].y += tt[j].y * kv[i].x;
                }
        }
    }
#pragma unroll
    for (int i = 0; i < 4; i++)
#pragma unroll
        for (int j = 0; j < 4; j++)
            g_Xqkv[(size_t)bh * 4096 + (eg2 + 16 * i) * 64 + (xg2 * 4 + j)] = c2[i][j];
}

// ============================================================================
// K4: xw[b,o,x] = sum_e xqkv[b,e,x] * (Wr+iWi)[h,e,o,x] — UNCHANGED from R12.
// ============================================================================
__global__ __launch_bounds__(256) void k_w(const float* __restrict__ Wr,
                                           const float* __restrict__ Wi)
{
    __shared__ float2 Xs[4][64][16];   // [bb][e][x16]  32KB
    const int tid = threadIdx.x;
    const int bx = blockIdx.x;
    const int h  = bx & 7;
    const int xq = (bx >> 3) & 3;      // x-quarter
    const int oh = (bx >> 5) & 1;      // o-half
    const int bq = bx >> 6;            // b-group of 4 (8 groups)

    for (int idx = tid; idx < 4096; idx += 256) {
        int bb = idx >> 10, rem = idx & 1023;
        int e = rem >> 4, xx = rem & 15;
        int b = bq * 4 + bb;
        Xs[bb][e][xx] = g_Xqkv[(size_t)(b * 8 + h) * 4096 + e * 64 + xq * 16 + xx];
    }
    __syncthreads();

    const int x  = tid & 15;           // mode (lane-contiguous -> coalesced W)
    const int og = tid >> 4;           // o = oh*32 + og*2 + i, i<2

    u64 acc[4][2];                     // [bb][i]
#pragma unroll
    for (int bb = 0; bb < 4; bb++)
#pragma unroll
        for (int i = 0; i < 2; i++) acc[bb][i] = 0ULL;

    const size_t base = ((size_t)(h * 64) * 64 + oh * 32 + og * 2) * 64 + xq * 16 + x;
    u64 wa[2][2], wb[2][2];
#pragma unroll
    for (int i = 0; i < 2; i++) {       // prologue: e=0
        float wr = __ldg(Wr + base + i * 64);
        float wi = __ldg(Wi + base + i * 64);
        wa[0][i] = pk2(wr, wi); wb[0][i] = pk2(wi, wr);
    }

    for (int e = 0; e < 64; e += 2) {
        size_t b1 = base + (size_t)(e + 1) * 4096;
#pragma unroll
        for (int i = 0; i < 2; i++) {
            float wr = __ldg(Wr + b1 + i * 64);
            float wi = __ldg(Wi + b1 + i * 64);
            wa[1][i] = pk2(wr, wi); wb[1][i] = pk2(wi, wr);
        }
#pragma unroll
        for (int bb = 0; bb < 4; bb++) {
            float2 xv = Xs[bb][e][x];
            u64 xr = pk2(xv.x, xv.x);
            u64 xm = pk2(-xv.y, xv.y);
#pragma unroll
            for (int i = 0; i < 2; i++) {
                acc[bb][i] = ffma2(xr, wa[0][i], acc[bb][i]);
                acc[bb][i] = ffma2(xm, wb[0][i], acc[bb][i]);
            }
        }
        if (e + 2 < 64) {
            size_t b2 = base + (size_t)(e + 2) * 4096;
#pragma unroll
            for (int i = 0; i < 2; i++) {
                float wr = __ldg(Wr + b2 + i * 64);
                float wi = __ldg(Wi + b2 + i * 64);
                wa[0][i] = pk2(wr, wi); wb[0][i] = pk2(wi, wr);
            }
        }
#pragma unroll
        for (int bb = 0; bb < 4; bb++) {
            float2 xv = Xs[bb][e + 1][x];
            u64 xr = pk2(xv.x, xv.x);
            u64 xm = pk2(-xv.y, xv.y);
#pragma unroll
            for (int i = 0; i < 2; i++) {
                acc[bb][i] = ffma2(xr, wa[1][i], acc[bb][i]);
                acc[bb][i] = ffma2(xm, wb[1][i], acc[bb][i]);
            }
        }
    }

#pragma unroll
    for (int bb = 0; bb < 4; bb++)
#pragma unroll
        for (int i = 0; i < 2; i++)
            g_Xw[(size_t)((bq * 4 + bb) * 8 + h) * 4096
                 + (oh * 32 + og * 2 + i) * 64 + xq * 16 + x] = upk2(acc[bb][i]);
}

// ============================================================================
// K5: pruned irfft, radix-2 output split, grid x2.
// NEW: odd-mode twiddle computed, not loaded: tO = tE * w^{n0+j}
// (wj preloaded per thread). LDS/iter 16 -> 12, kkO ALU gone; +16 scalar FFMA.
// Shifts the kernel off its LDS-issue bound toward the fma pipe.
// ============================================================================
__global__ __launch_bounds__(256) void k_irfft(float* __restrict__ out)
{
    __shared__ float2 Xs[64 * 65];   // [o][m], pitch 65 -> conflict-free
    __shared__ float2 tw[1024];      // (cos, sin)(2pi k/1024)
    const int tid = threadIdx.x;
    const int bh = blockIdx.x >> 1, half = blockIdx.x & 1;
    for (int k0 = tid; k0 < 1024; k0 += 256) {
        float s, c;
        sincosf(6.2831853071795864769f * (float)k0 * (1.0f / 1024.0f), &s, &c);
        tw[k0] = make_float2(c, s);
    }
    const float2* src = g_Xw + (size_t)bh * 4096;
    const float S1 = 1.0f / 268435456.0f;   // 2^-28
    for (int idx = tid; idx < 4096; idx += 256) {
        int o = idx >> 6, m = idx & 63;
        float2 v = src[idx];
        float sc = (m == 0) ? S1 : 2.0f * S1;
        Xs[o * 65 + m] = make_float2(v.x * sc, -v.y * sc);
    }
    __syncthreads();

    const int og = tid & 15;   // o = og + 16*i
    const int ng = tid >> 4;   // n tile base (const per half-warp -> tw broadcast)
    float* obase = out + (size_t)bh * 65536;

    for (int nc = half * 4; nc < half * 4 + 4; nc++) {
        const int n0 = nc * 64 + ng * 4;   // < 512
        float2 wj[4];                       // w^{n0+j}
#pragma unroll
        for (int j = 0; j < 4; j++) wj[j] = tw[(n0 + j) & 1023];

        u64 accE[4][4], accO[4][4];
#pragma unroll
        for (int i = 0; i < 4; i++)
#pragma unroll
            for (int j = 0; j < 4; j++) { accE[i][j] = 0ULL; accO[i][j] = 0ULL; }

#pragma unroll 2
        for (int m = 0; m < 64; m += 2) {
            u64 xwE[4], xwO[4];
#pragma unroll
            for (int i = 0; i < 4; i++) {
                xwE[i] = *(const u64*)&Xs[(og + 16 * i) * 65 + m];
                xwO[i] = *(const u64*)&Xs[(og + 16 * i) * 65 + m + 1];
            }
            int kkE = (m * n0) & 1023;
#pragma unroll
            for (int j = 0; j < 4; j++) {
                u64 tE = *(const u64*)&tw[kkE];
                float2 te = upk2(tE);
                // tO = tE * wj  (exact complex multiply, 4 fma-pipe ops)
                float t1   = te.x * wj[j].x;
                float tore = fmaf(-te.y, wj[j].y, t1);
                float t2   = te.x * wj[j].y;
                float toim = fmaf(te.y, wj[j].x, t2);
                u64 tO = pk2(tore, toim);
                accE[0][j] = ffma2(xwE[0], tE, accE[0][j]);
                accE[1][j] = ffma2(xwE[1], tE, accE[1][j]);
                accE[2][j] = ffma2(xwE[2], tE, accE[2][j]);
                accE[3][j] = ffma2(xwE[3], tE, accE[3][j]);
                accO[0][j] = ffma2(xwO[0], tO, accO[0][j]);
                accO[1][j] = ffma2(xwO[1], tO, accO[1][j]);
                accO[2][j] = ffma2(xwO[2], tO, accO[2][j]);
                accO[3][j] = ffma2(xwO[3], tO, accO[3][j]);
                kkE = (kkE + m) & 1023;
            }
        }
#pragma unroll
        for (int i = 0; i < 4; i++) {
            float4 rlo, rhi;
#pragma unroll
            for (int j = 0; j < 4; j++) {
                float2 ev = upk2(accE[i][j]);
                float2 ov = upk2(accO[i][j]);
                float e = ev.x + ev.y, o = ov.x + ov.y;
                ((float*)&rlo)[j] = e + o;
                ((float*)&rhi)[j] = e - o;
            }
            float* row = obase + (size_t)(og + 16 * i) * 1024;
            *(float4*)(row + n0)       = rlo;
            *(float4*)(row + n0 + 512) = rhi;
        }
    }
}

// ============================================================================
extern "C" void kernel_launch(void* const* d_in, const int* in_sizes, int n_in,
                              void* d_out, int out_size)
{
    const float* q  = (const float*)d_in[0];
    const float* k  = (const float*)d_in[1];
    // d_in[2] = v : unused by the reference math
    const float* Wr = (const float*)d_in[3];
    const float* Wi = (const float*)d_in[4];
    float* out = (float*)d_out;

    k_dft  <<<dim3(BHN, 2), 256>>>(q, k);
    k_qk2  <<<BHN, 256>>>();
    k_w    <<<BHN * 2, 256>>>(Wr, Wi);
    k_irfft<<<BHN * 2, 256>>>(out);
}

// round 17
// speedup vs baseline: 1.0468x; 1.0468x over previous
#include <cuda_runtime.h>

// Problem constants: B=32, H=8, E=64, L=1024, MODES=64, OUT/8=64
#define BHN 256           // B*H
typedef unsigned long long u64;

// Scratch (allocation-free: device globals).
__device__ float2 g_Xq[BHN * 4096];
__device__ float2 g_Xk[BHN * 4096];
__device__ float2 g_Xqkv[BHN * 4096];
__device__ float2 g_Xw[BHN * 4096];

// ---- packed f32x2 helpers (Blackwell FFMA2 path) ----
__device__ __forceinline__ u64 pk2(float lo, float hi) {
    u64 r; asm("mov.b64 %0,{%1,%2};" : "=l"(r) : "f"(lo), "f"(hi)); return r;
}
__device__ __forceinline__ float2 upk2(u64 v) {
    float2 r; asm("mov.b64 {%0,%1},%2;" : "=f"(r.x), "=f"(r.y) : "l"(v)); return r;
}
__device__ __forceinline__ u64 ffma2(u64 a, u64 b, u64 c) {
    u64 d; asm("fma.rn.f32x2 %0,%1,%2,%3;" : "=l"(d) : "l"(a), "l"(b), "l"(c)); return d;
}
__device__ __forceinline__ u64 fadd2(u64 a, u64 b) {
    u64 d; asm("add.rn.f32x2 %0,%1,%2;" : "=l"(d) : "l"(a), "l"(b)); return d;
}

// ============================================================================
// K1: pruned rDFT, radix-2 decimation (PROVEN Round-12 version, reverted):
//   X[m] = sum_{l<512} y[l] w^{ml},  y = s (m even) / d (m odd)
// 64-l chunks (8 sync rounds), float4 ss/dd, conflict-free staging.
// ============================================================================
__global__ __launch_bounds__(256) void k_dft(const float* __restrict__ qp,
                                             const float* __restrict__ kp)
{
    __shared__ float2 tw[1024];    // e^{-2pi i k/1024}  (8KB)
    __shared__ float4 ss[1024];    // s chunk: [l 0..63][e-group 0..15] (16KB)
    __shared__ float4 dd[1024];    // d chunk (16KB)
    const int tid = threadIdx.x;
    const int bh = blockIdx.x;
    const int b = bh >> 3, h = bh & 7;
    const float* src = (blockIdx.y == 0 ? qp : kp) + (size_t)b * 524288 + h * 64;
    float2* dst = (blockIdx.y == 0 ? g_Xq : g_Xk) + (size_t)bh * 4096;

    for (int k0 = tid; k0 < 1024; k0 += 256) {
        float s, c;
        sincosf(-6.2831853071795864769f * (float)k0 * (1.0f / 1024.0f), &s, &c);
        tw[k0] = make_float2(c, s);
    }

    const int eg = tid & 15;       // e group: e = eg*4 + i   (varies per lane)
    const int mg = tid >> 4;       // m group: m = mg + 16*j  (const per half-warp)
    const float4* ybase = (mg & 1) ? dd : ss;   // parity(m) == parity(mg)

    u64 acc[4][4];
#pragma unroll
    for (int i = 0; i < 4; i++)
#pragma unroll
        for (int j = 0; j < 4; j++) acc[i][j] = 0ULL;

    for (int c0 = 0; c0 < 8; c0++) {
        __syncthreads();
        for (int idx = tid; idx < 1024; idx += 256) {
            int l = idx >> 4, e4 = idx & 15;
            size_t off = (size_t)(c0 * 64 + l) * 512 + e4 * 4;
            float4 a = *(const float4*)(src + off);
            float4 bb4 = *(const float4*)(src + off + 262144);  // l+512
            ss[idx] = make_float4(a.x + bb4.x, a.y + bb4.y, a.z + bb4.z, a.w + bb4.w);
            dd[idx] = make_float4(a.x - bb4.x, a.y - bb4.y, a.z - bb4.z, a.w - bb4.w);
        }
        __syncthreads();

        u64 cacc[4][4];   // chunk accumulators (2-level sum: fp32 accuracy)
#pragma unroll
        for (int i = 0; i < 4; i++)
#pragma unroll
            for (int j = 0; j < 4; j++) cacc[i][j] = 0ULL;

#pragma unroll 8
        for (int l = 0; l < 64; l++) {
            const int lg = c0 * 64 + l;
            float4 xv = ybase[l * 16 + eg];
            u64 x0 = pk2(xv.x, xv.x), x1 = pk2(xv.y, xv.y);
            u64 x2 = pk2(xv.z, xv.z), x3 = pk2(xv.w, xv.w);
            int kk = (mg * lg) & 1023;
            const int dk = (lg << 4) & 1023;
#pragma unroll
            for (int j = 0; j < 4; j++) {
                u64 t = *(const u64*)&tw[kk];
                cacc[0][j] = ffma2(x0, t, cacc[0][j]);
                cacc[1][j] = ffma2(x1, t, cacc[1][j]);
                cacc[2][j] = ffma2(x2, t, cacc[2][j]);
                cacc[3][j] = ffma2(x3, t, cacc[3][j]);
                kk = (kk + dk) & 1023;
            }
        }
#pragma unroll
        for (int i = 0; i < 4; i++)
#pragma unroll
            for (int j = 0; j < 4; j++) acc[i][j] = fadd2(acc[i][j], cacc[i][j]);
    }

#pragma unroll
    for (int i = 0; i < 4; i++)
#pragma unroll
        for (int j = 0; j < 4; j++)
            dst[(eg * 4 + i) * 64 + (mg + 16 * j)] = upk2(acc[i][j]);
}

// ============================================================================
// K2 (fused qk + qkv) — UNCHANGED:
//   phase 1: xqk[x,y] = sum_e Xq[e,x]*Xk[e,y]; complex tanh -> T (in smem)
//   phase 2: xqkv[e,x] = sum_y T[x,y]*Xk[e,y]
// ============================================================================
__global__ __launch_bounds__(256) void k_qk2(void)
{
    __shared__ float2 buf[4096];     // phase1: Aq|Ak; phase2: Ts pitch 64
    __shared__ float2 Bk[64 * 17];   // [e][yy] pitch 17
    const int tid = threadIdx.x, bh = blockIdx.x;
    const float2* xq = g_Xq + (size_t)bh * 4096;
    const float2* xk = g_Xk + (size_t)bh * 4096;
    const int xg = tid & 15, yg = tid >> 4;

    float2 c[4][4];
#pragma unroll
    for (int i = 0; i < 4; i++)
#pragma unroll
        for (int j = 0; j < 4; j++) c[i][j] = make_float2(0.f, 0.f);

    for (int s = 0; s < 2; s++) {
        __syncthreads();
        for (int idx = tid; idx < 2048; idx += 256) {
            buf[idx]        = xq[s * 2048 + idx];
            buf[2048 + idx] = xk[s * 2048 + idx];
        }
        __syncthreads();
        for (int e = 0; e < 32; e++) {
            float4 a01 = *(const float4*)&buf[e * 64 + xg * 4];
            float4 a23 = *(const float4*)&buf[e * 64 + xg * 4 + 2];
            float4 b01 = *(const float4*)&buf[2048 + e * 64 + yg * 4];
            float4 b23 = *(const float4*)&buf[2048 + e * 64 + yg * 4 + 2];
            float2 aq[4] = { {a01.x,a01.y},{a01.z,a01.w},{a23.x,a23.y},{a23.z,a23.w} };
            float2 ak[4] = { {b01.x,b01.y},{b01.z,b01.w},{b23.x,b23.y},{b23.z,b23.w} };
#pragma unroll
            for (int i = 0; i < 4; i++)
#pragma unroll
                for (int j = 0; j < 4; j++) {
                    c[i][j].x += aq[i].x * ak[j].x;
                    c[i][j].x -= aq[i].y * ak[j].y;
                    c[i][j].y += aq[i].x * ak[j].y;
                    c[i][j].y += aq[i].y * ak[j].x;
                }
        }
    }

    float2 treg[4][4];
#pragma unroll
    for (int i = 0; i < 4; i++)
#pragma unroll
        for (int j = 0; j < 4; j++) {
            float t = tanhf(c[i][j].x);
            float u = tanf(c[i][j].y);
            float u2 = u * u;
            float rr, ii;
            if (!(u2 < 1e30f)) { rr = 1.0f / t; ii = 0.0f; }
            else {
                float inv = 1.0f / fmaf(t * t, u2, 1.0f);
                rr = t * (1.0f + u2) * inv;
                ii = u * (1.0f - t * t) * inv;
            }
            treg[i][j] = make_float2(rr, ii);
        }
    __syncthreads();                 // all phase-1 reads of buf done
#pragma unroll
    for (int i = 0; i < 4; i++)
#pragma unroll
        for (int j = 0; j < 4; j++)
            buf[(xg * 4 + i) * 64 + yg * 4 + j] = treg[i][j];   // Ts[x][y]

    const int eg2 = tid & 15, xg2 = tid >> 4;   // e = eg2+16i, x = xg2*4+j
    float2 c2[4][4];
#pragma unroll
    for (int i = 0; i < 4; i++)
#pragma unroll
        for (int j = 0; j < 4; j++) c2[i][j] = make_float2(0.f, 0.f);

    for (int ys = 0; ys < 4; ys++) {
        __syncthreads();
        for (int idx = tid; idx < 1024; idx += 256) {
            int r = idx >> 4, yy = idx & 15;
            Bk[r * 17 + yy] = xk[r * 64 + ys * 16 + yy];
        }
        __syncthreads();
        for (int y = 0; y < 16; y++) {
            float2 kv[4], tt[4];
#pragma unroll
            for (int i = 0; i < 4; i++) kv[i] = Bk[(eg2 + 16 * i) * 17 + y];
#pragma unroll
            for (int j = 0; j < 4; j++) tt[j] = buf[(xg2 * 4 + j) * 64 + ys * 16 + y];
#pragma unroll
            for (int i = 0; i < 4; i++)
#pragma unroll
                for (int j = 0; j < 4; j++) {
                    c2[i][j].x += tt[j].x * kv[i].x;
                    c2[i][j].x -= tt[j].y * kv[i].y;
                    c2[i][j].y += tt[j].x * kv[i].y;
                    c2[i][j].y += tt[j].y * kv[i].x;
                }
        }
    }
#pragma unroll
    for (int i = 0; i < 4; i++)
#pragma unroll
        for (int j = 0; j < 4; j++)
            g_Xqkv[(size_t)bh * 4096 + (eg2 + 16 * i) * 64 + (xg2 * 4 + j)] = c2[i][j];
}

// ============================================================================
// K4: xw[b,o,x] = sum_e xqkv[b,e,x] * (Wr+iWi)[h,e,o,x] — UNCHANGED.
// o-split grid 512, double-buffered W prefetch.
// ============================================================================
__global__ __launch_bounds__(256) void k_w(const float* __restrict__ Wr,
                                           const float* __restrict__ Wi)
{
    __shared__ float2 Xs[4][64][16];   // [bb][e][x16]  32KB
    const int tid = threadIdx.x;
    const int bx = blockIdx.x;
    const int h  = bx & 7;
    const int xq = (bx >> 3) & 3;      // x-quarter
    const int oh = (bx >> 5) & 1;      // o-half
    const int bq = bx >> 6;            // b-group of 4 (8 groups)

    for (int idx = tid; idx < 4096; idx += 256) {
        int bb = idx >> 10, rem = idx & 1023;
        int e = rem >> 4, xx = rem & 15;
        int b = bq * 4 + bb;
        Xs[bb][e][xx] = g_Xqkv[(size_t)(b * 8 + h) * 4096 + e * 64 + xq * 16 + xx];
    }
    __syncthreads();

    const int x  = tid & 15;           // mode (lane-contiguous -> coalesced W)
    const int og = tid >> 4;           // o = oh*32 + og*2 + i, i<2

    u64 acc[4][2];                     // [bb][i]
#pragma unroll
    for (int bb = 0; bb < 4; bb++)
#pragma unroll
        for (int i = 0; i < 2; i++) acc[bb][i] = 0ULL;

    const size_t base = ((size_t)(h * 64) * 64 + oh * 32 + og * 2) * 64 + xq * 16 + x;
    u64 wa[2][2], wb[2][2];
#pragma unroll
    for (int i = 0; i < 2; i++) {       // prologue: e=0
        float wr = __ldg(Wr + base + i * 64);
        float wi = __ldg(Wi + base + i * 64);
        wa[0][i] = pk2(wr, wi); wb[0][i] = pk2(wi, wr);
    }

    for (int e = 0; e < 64; e += 2) {
        size_t b1 = base + (size_t)(e + 1) * 4096;
#pragma unroll
        for (int i = 0; i < 2; i++) {
            float wr = __ldg(Wr + b1 + i * 64);
            float wi = __ldg(Wi + b1 + i * 64);
            wa[1][i] = pk2(wr, wi); wb[1][i] = pk2(wi, wr);
        }
#pragma unroll
        for (int bb = 0; bb < 4; bb++) {
            float2 xv = Xs[bb][e][x];
            u64 xr = pk2(xv.x, xv.x);
            u64 xm = pk2(-xv.y, xv.y);
#pragma unroll
            for (int i = 0; i < 2; i++) {
                acc[bb][i] = ffma2(xr, wa[0][i], acc[bb][i]);
                acc[bb][i] = ffma2(xm, wb[0][i], acc[bb][i]);
            }
        }
        if (e + 2 < 64) {
            size_t b2 = base + (size_t)(e + 2) * 4096;
#pragma unroll
            for (int i = 0; i < 2; i++) {
                float wr = __ldg(Wr + b2 + i * 64);
                float wi = __ldg(Wi + b2 + i * 64);
                wa[0][i] = pk2(wr, wi); wb[0][i] = pk2(wi, wr);
            }
        }
#pragma unroll
        for (int bb = 0; bb < 4; bb++) {
            float2 xv = Xs[bb][e + 1][x];
            u64 xr = pk2(xv.x, xv.x);
            u64 xm = pk2(-xv.y, xv.y);
#pragma unroll
            for (int i = 0; i < 2; i++) {
                acc[bb][i] = ffma2(xr, wa[1][i], acc[bb][i]);
                acc[bb][i] = ffma2(xm, wb[1][i], acc[bb][i]);
            }
        }
    }

#pragma unroll
    for (int bb = 0; bb < 4; bb++)
#pragma unroll
        for (int i = 0; i < 2; i++)
            g_Xw[(size_t)((bq * 4 + bb) * 8 + h) * 4096
                 + (oh * 32 + og * 2 + i) * 64 + xq * 16 + x] = upk2(acc[bb][i]);
}

// ============================================================================
// K5: pruned irfft, radix-2 output split, grid x2. KEPT (measured win):
// odd-mode twiddle computed, not loaded: tO = tE * w^{n0+j}.
// ============================================================================
__global__ __launch_bounds__(256) void k_irfft(float* __restrict__ out)
{
    __shared__ float2 Xs[64 * 65];   // [o][m], pitch 65 -> conflict-free
    __shared__ float2 tw[1024];      // (cos, sin)(2pi k/1024)
    const int tid = threadIdx.x;
    const int bh = blockIdx.x >> 1, half = blockIdx.x & 1;
    for (int k0 = tid; k0 < 1024; k0 += 256) {
        float s, c;
        sincosf(6.2831853071795864769f * (float)k0 * (1.0f / 1024.0f), &s, &c);
        tw[k0] = make_float2(c, s);
    }
    const float2* src = g_Xw + (size_t)bh * 4096;
    const float S1 = 1.0f / 268435456.0f;   // 2^-28
    for (int idx = tid; idx < 4096; idx += 256) {
        int o = idx >> 6, m = idx & 63;
        float2 v = src[idx];
        float sc = (m == 0) ? S1 : 2.0f * S1;
        Xs[o * 65 + m] = make_float2(v.x * sc, -v.y * sc);
    }
    __syncthreads();

    const int og = tid & 15;   // o = og + 16*i
    const int ng = tid >> 4;   // n tile base (const per half-warp -> tw broadcast)
    float* obase = out + (size_t)bh * 65536;

    for (int nc = half * 4; nc < half * 4 + 4; nc++) {
        const int n0 = nc * 64 + ng * 4;   // < 512
        float2 wj[4];                       // w^{n0+j}
#pragma unroll
        for (int j = 0; j < 4; j++) wj[j] = tw[(n0 + j) & 1023];

        u64 accE[4][4], accO[4][4];
#pragma unroll
        for (int i = 0; i < 4; i++)
#pragma unroll
            for (int j = 0; j < 4; j++) { accE[i][j] = 0ULL; accO[i][j] = 0ULL; }

#pragma unroll 2
        for (int m = 0; m < 64; m += 2) {
            u64 xwE[4], xwO[4];
#pragma unroll
            for (int i = 0; i < 4; i++) {
                xwE[i] = *(const u64*)&Xs[(og + 16 * i) * 65 + m];
                xwO[i] = *(const u64*)&Xs[(og + 16 * i) * 65 + m + 1];
            }
            int kkE = (m * n0) & 1023;
#pragma unroll
            for (int j = 0; j < 4; j++) {
                u64 tE = *(const u64*)&tw[kkE];
                float2 te = upk2(tE);
                // tO = tE * wj  (exact complex multiply, 4 fma-pipe ops)
                float t1   = te.x * wj[j].x;
                float tore = fmaf(-te.y, wj[j].y, t1);
                float t2   = te.x * wj[j].y;
                float toim = fmaf(te.y, wj[j].x, t2);
                u64 tO = pk2(tore, toim);
                accE[0][j] = ffma2(xwE[0], tE, accE[0][j]);
                accE[1][j] = ffma2(xwE[1], tE, accE[1][j]);
                accE[2][j] = ffma2(xwE[2], tE, accE[2][j]);
                accE[3][j] = ffma2(xwE[3], tE, accE[3][j]);
                accO[0][j] = ffma2(xwO[0], tO, accO[0][j]);
                accO[1][j] = ffma2(xwO[1], tO, accO[1][j]);
                accO[2][j] = ffma2(xwO[2], tO, accO[2][j]);
                accO[3][j] = ffma2(xwO[3], tO, accO[3][j]);
                kkE = (kkE + m) & 1023;
            }
        }
#pragma unroll
        for (int i = 0; i < 4; i++) {
            float4 rlo, rhi;
#pragma unroll
            for (int j = 0; j < 4; j++) {
                float2 ev = upk2(accE[i][j]);
                float2 ov = upk2(accO[i][j]);
                float e = ev.x + ev.y, o = ov.x + ov.y;
                ((float*)&rlo)[j] = e + o;
                ((float*)&rhi)[j] = e - o;
            }
            float* row = obase + (size_t)(og + 16 * i) * 1024;
            *(float4*)(row + n0)       = rlo;
            *(float4*)(row + n0 + 512) = rhi;
        }
    }
}

// ============================================================================
extern "C" void kernel_launch(void* const* d_in, const int* in_sizes, int n_in,
                              void* d_out, int out_size)
{
    const float* q  = (const float*)d_in[0];
    const float* k  = (const float*)d_in[1];
    // d_in[2] = v : unused by the reference math
    const float* Wr = (const float*)d_in[3];
    const float* Wi = (const float*)d_in[4];
    float* out = (float*)d_out;

    k_dft  <<<dim3(BHN, 2), 256>>>(q, k);
    k_qk2  <<<BHN, 256>>>();
    k_w    <<<BHN * 2, 256>>>(Wr, Wi);
    k_irfft<<<BHN * 2, 256>>>(out);
}